// round 15
// baseline (speedup 1.0000x reference)
#include <cuda_runtime.h>
#include <cuda_bf16.h>
#include <cstdint>

#define NPTS 65536
#define KC   4096
#define DIM  128
#define BN   256          // rows per CTA
#define BK   128
#define NT   (KC / BK)    // 32 tiles
#define CAP  (1 << 24)

// Device scratch (allocation-free rule)
__device__ __nv_bfloat16 g_a0[NPTS * DIM];
__device__ __nv_bfloat16 g_b0[KC * DIM];
__device__ __align__(16) float2 g_an[NPTS];  // {2||a1||, 2||a0||}
__device__ __align__(16) float2 g_bn[KC];    // {||b||, ||b1||}
__device__ __align__(16) float  g_c2[KC];    // exact ||b||^2
__device__ float g_bmax[2];
__device__ float g_bestval[NPTS];            // sampled approx-min (upper bound)
__device__ unsigned long long g_best[NPTS];
__device__ int g_cnt[1];
__device__ uint32_t g_list[CAP];             // (n<<12)|k

// ---------------------------------------------------------------------------
__device__ __forceinline__ uint32_t smem_u32(const void* p) {
    uint32_t a;
    asm("{ .reg .u64 t; cvta.to.shared.u64 t, %1; cvt.u32.u64 %0, t; }"
        : "=r"(a) : "l"(p));
    return a;
}
__device__ __forceinline__ uint32_t fkey(float f) {
    uint32_t u = __float_as_uint(f);
    return (u & 0x80000000u) ? ~u : (u | 0x80000000u);
}
#define LDSM_X4(r0, r1, r2, r3, addr) \
    asm volatile("ldmatrix.sync.aligned.m8n8.x4.shared.b16 {%0,%1,%2,%3}, [%4];" \
                 : "=r"(r0), "=r"(r1), "=r"(r2), "=r"(r3) : "r"(addr))
#define MMA_BF16(c, a, b0v, b1v) \
    asm volatile("mma.sync.aligned.m16n8k16.row.col.f32.bf16.bf16.f32 " \
                 "{%0,%1,%2,%3}, {%4,%5,%6,%7}, {%8,%9}, {%0,%1,%2,%3};" \
                 : "+f"((c)[0]), "+f"((c)[1]), "+f"((c)[2]), "+f"((c)[3]) \
                 : "r"((a)[0]), "r"((a)[1]), "r"((a)[2]), "r"((a)[3]), \
                   "r"(b0v), "r"(b1v))
__device__ __forceinline__ void cp16(uint32_t dst, const void* src) {
    asm volatile("cp.async.cg.shared.global [%0], [%1], 16;"
                 :: "r"(dst), "l"(src));
}
#define CP_COMMIT() asm volatile("cp.async.commit_group;" ::: "memory")
#define CP_WAIT0()  asm volatile("cp.async.wait_group 0;" ::: "memory")

// ---------------------------------------------------------------------------
// Prologues (identical to R12/R13 — validated rel_err 0.0)
// ---------------------------------------------------------------------------
__global__ void prep_a(const float* __restrict__ in) {
    int row  = blockIdx.x * 8 + (threadIdx.x >> 5);
    int lane = threadIdx.x & 31;
    float4 v = ((const float4*)(in + (size_t)row * DIM))[lane];
    float va[4] = {v.x, v.y, v.z, v.w};
    __nv_bfloat16 h[4];
    float n0 = 0.f, n1 = 0.f;
    #pragma unroll
    for (int j = 0; j < 4; ++j) {
        h[j] = __float2bfloat16(va[j]);
        float a0 = __bfloat162float(h[j]);
        float r  = va[j] - a0;
        n0 = fmaf(a0, a0, n0);
        n1 = fmaf(r, r, n1);
    }
    *(uint2*)(g_a0 + (size_t)row * DIM + lane * 4) = *(const uint2*)h;
    #pragma unroll
    for (int o = 16; o; o >>= 1) {
        n0 += __shfl_xor_sync(~0u, n0, o);
        n1 += __shfl_xor_sync(~0u, n1, o);
    }
    if (lane == 0) g_an[row] = make_float2(2.f * sqrtf(n1), 2.f * sqrtf(n0));
}
__global__ void prep_b(const float* __restrict__ in) {
    int row  = blockIdx.x * 8 + (threadIdx.x >> 5);
    int lane = threadIdx.x & 31;
    float4 v = ((const float4*)(in + (size_t)row * DIM))[lane];
    float va[4] = {v.x, v.y, v.z, v.w};
    __nv_bfloat16 h[4];
    float nb = 0.f, n1 = 0.f;
    #pragma unroll
    for (int j = 0; j < 4; ++j) {
        h[j] = __float2bfloat16(va[j]);
        float b0 = __bfloat162float(h[j]);
        float r  = va[j] - b0;
        nb = fmaf(va[j], va[j], nb);
        n1 = fmaf(r, r, n1);
    }
    *(uint2*)(g_b0 + (size_t)row * DIM + lane * 4) = *(const uint2*)h;
    #pragma unroll
    for (int o = 16; o; o >>= 1) {
        nb += __shfl_xor_sync(~0u, nb, o);
        n1 += __shfl_xor_sync(~0u, n1, o);
    }
    if (lane == 0) {
        g_c2[row] = nb;
        g_bn[row] = make_float2(sqrtf(nb), sqrtf(n1));
    }
}
__global__ void reduce_kernel() {
    __shared__ float s0[512], s1[512];
    int t = threadIdx.x;
    float m0 = 0.f, m1 = 0.f;
    for (int k = t; k < KC; k += 512) {
        float2 b = g_bn[k];
        m0 = fmaxf(m0, b.x);
        m1 = fmaxf(m1, b.y);
    }
    s0[t] = m0; s1[t] = m1;
    __syncthreads();
    for (int o = 256; o; o >>= 1) {
        if (t < o) {
            s0[t] = fmaxf(s0[t], s0[t + o]);
            s1[t] = fmaxf(s1[t], s1[t + o]);
        }
        __syncthreads();
    }
    if (t == 0) { g_bmax[0] = s0[0]; g_bmax[1] = s1[0]; g_cnt[0] = 0; }
}
__global__ void init_best_kernel() {
    int i = blockIdx.x * blockDim.x + threadIdx.x;
    if (i < NPTS) g_best[i] = 0xFFFFFFFFFFFFFFFFull;
}
__global__ void final_kernel(float* __restrict__ out) {
    int i = blockIdx.x * blockDim.x + threadIdx.x;
    if (i < NPTS) out[i] = (float)(uint32_t)(g_best[i] & 0xFFFFFFFFull);
}

// ---------------------------------------------------------------------------
// Phase GEMM (R13-validated LDSM path): 1-pass a0*b0 HMMA, BN=256.
// PHASE=1: SAMPLED k-tiles {0,8,16,24} -> per-row upper bound g_bestval.
// PHASE=2: all 32 tiles; push (n,k) with s <= thr + margin(n,k).
// 512 threads = 16 warps, 4(M) x 4(N); warp tile 64(M) x 32(N).
// smem: A @0 (64K), B double-buffer @64K/96K, c2 @128K (16K). 144 KB.
// ---------------------------------------------------------------------------
template <int PHASE>
__global__ __launch_bounds__(512) void phase_kernel() {
    extern __shared__ char smem[];
    const uint32_t sbase = smem_u32(smem);

    const int tid = threadIdx.x;
    const int L   = tid & 31;
    const int wid = tid >> 5;
    const int wm  = wid & 3;
    const int wn  = wid >> 2;
    const int n0  = blockIdx.x * BN;

    // stage A once: 256 rows x 256B, swizzled (plain stores — validated)
    #pragma unroll
    for (int it = 0; it < 8; ++it) {
        int Gi = tid + it * 512;
        int row = Gi >> 4, g = Gi & 15;
        uint4 v = *((const uint4*)(g_a0 + (size_t)(n0 + row) * DIM) + g);
        *(uint4*)(smem + row * 256 + ((g ^ (row & 7)) << 4)) = v;
    }
    // stage full-K c2 once (16 KB)
    #pragma unroll
    for (int it = 0; it < 2; ++it) {
        int Gi = tid + it * 512;
        cp16(sbase + 131072 + Gi * 16, g_c2 + Gi * 4);
    }
    const float* c2s = (const float*)(smem + 131072);

    auto stage_b = [&](int st, int k0) {
        #pragma unroll
        for (int it = 0; it < 4; ++it) {
            int Gi = tid + it * 512;
            int row = Gi >> 4, g = Gi & 15;
            uint32_t dst = sbase + 65536 + st * 32768 +
                           row * 256 + ((g ^ (row & 7)) << 4);
            cp16(dst, g_b0 + (size_t)(k0 + row) * DIM + g * 8);
        }
    };
    stage_b(0, 0);
    CP_COMMIT();

    // ldmatrix lane constants (validated R7-R13)
    const int aRow = ((L >> 3) & 1) * 8 + (L & 7);
    const int aG   = L >> 4;
    const int sxa  = (L & 7);
    const int bRow = (L >> 4) * 8 + (L & 7);
    const int bG   = (L >> 3) & 1;
    const int sxb  = (L & 7);
    uint32_t aAddrB[4];
    #pragma unroll
    for (int bi = 0; bi < 4; ++bi)
        aAddrB[bi] = sbase + (64 * wm + 16 * bi + aRow) * 256;
    const uint32_t bOff = (32 * wn + bRow) * 256;

    float rval[4][2];
    float anx[4][2], any[4][2], thr[4][2];
    #pragma unroll
    for (int bi = 0; bi < 4; ++bi)
        #pragma unroll
        for (int h = 0; h < 2; ++h) {
            rval[bi][h] = 3.0e38f;
            if (PHASE == 2) {
                int nr = n0 + 64 * wm + 16 * bi + 8 * h + (L >> 2);
                float2 an = g_an[nr];
                anx[bi][h] = an.x; any[bi][h] = an.y;
                thr[bi][h] = g_bestval[nr] + an.x * g_bmax[0] +
                             an.y * g_bmax[1] + 0.02f;
            }
        }

    // PHASE 1: 4 sampled tiles (k-tile stride 8). PHASE 2: all 32.
    const int NTILES  = (PHASE == 1) ? 4 : NT;
    const int KSTRIDE = (PHASE == 1) ? 8 * BK : BK;

    for (int kt = 0; kt < NTILES; ++kt) {
        const int st = kt & 1;
        const int k0 = kt * KSTRIDE;

        CP_WAIT0();
        __syncthreads();
        if (kt + 1 < NTILES) { stage_b(st ^ 1, k0 + KSTRIDE); CP_COMMIT(); }

        const uint32_t bAddr = sbase + 65536 + st * 32768 + bOff;

        float acc[4][4][4];
        #pragma unroll
        for (int bi = 0; bi < 4; ++bi)
            #pragma unroll
            for (int nb = 0; nb < 4; ++nb)
                #pragma unroll
                for (int c = 0; c < 4; ++c) acc[bi][nb][c] = 0.0f;

        #pragma unroll
        for (int kk = 0; kk < 8; ++kk) {
            uint32_t a[4][4];
            #pragma unroll
            for (int bi = 0; bi < 4; ++bi) {
                uint32_t ad = aAddrB[bi] + (((2 * kk + aG) ^ sxa) << 4);
                LDSM_X4(a[bi][0], a[bi][1], a[bi][2], a[bi][3], ad);
            }
            uint32_t b[2][4];
            #pragma unroll
            for (int i2 = 0; i2 < 2; ++i2) {
                uint32_t bd = bAddr + i2 * 4096 + (((2 * kk + bG) ^ sxb) << 4);
                LDSM_X4(b[i2][0], b[i2][1], b[i2][2], b[i2][3], bd);
            }
            #pragma unroll
            for (int bi = 0; bi < 4; ++bi)
                #pragma unroll
                for (int nb = 0; nb < 4; ++nb) {
                    const uint32_t* q = b[nb >> 1];
                    if (nb & 1) MMA_BF16(acc[bi][nb], a[bi], q[2], q[3]);
                    else        MMA_BF16(acc[bi][nb], a[bi], q[0], q[1]);
                }
        }

        // ---- epilogue (k ascends; strict '<'/exact-rescore = first occ) ----
        #pragma unroll
        for (int nb = 0; nb < 4; ++nb) {
            int kc = k0 + 32 * wn + 8 * nb + 2 * (L & 3);
            float c2a = c2s[kc], c2b = c2s[kc + 1];
            float4 bn4;
            if (PHASE == 2)
                bn4 = __ldg((const float4*)(g_bn + kc));
            #pragma unroll
            for (int bi = 0; bi < 4; ++bi)
                #pragma unroll
                for (int h = 0; h < 2; ++h) {
                    float s0 = fmaf(-2.0f, acc[bi][nb][h * 2 + 0], c2a);
                    float s1 = fmaf(-2.0f, acc[bi][nb][h * 2 + 1], c2b);
                    if (PHASE == 1) {
                        rval[bi][h] = fminf(rval[bi][h], fminf(s0, s1));
                    } else {
                        int nr = n0 + 64 * wm + 16 * bi + 8 * h + (L >> 2);
                        if (s0 <= fmaf(anx[bi][h], bn4.x,
                                       fmaf(any[bi][h], bn4.y, thr[bi][h]))) {
                            int p = atomicAdd(g_cnt, 1);
                            if (p < CAP)
                                g_list[p] = ((uint32_t)nr << 12) | (uint32_t)kc;
                        }
                        if (s1 <= fmaf(anx[bi][h], bn4.z,
                                       fmaf(any[bi][h], bn4.w, thr[bi][h]))) {
                            int p = atomicAdd(g_cnt, 1);
                            if (p < CAP)
                                g_list[p] = ((uint32_t)nr << 12) | (uint32_t)(kc + 1);
                        }
                    }
                }
        }
    }

    if (PHASE == 1) {
        __syncthreads();
        float* rv = (float*)smem;     // reuse A region: 256 x 16 slots
        #pragma unroll
        for (int bi = 0; bi < 4; ++bi)
            #pragma unroll
            for (int h = 0; h < 2; ++h) {
                int row  = 64 * wm + 16 * bi + 8 * h + (L >> 2);
                int slot = wn * 4 + (L & 3);
                rv[row * 16 + slot] = rval[bi][h];
            }
        __syncthreads();
        if (tid < BN) {
            float bv = rv[tid * 16];
            #pragma unroll
            for (int c = 1; c < 16; ++c) bv = fminf(bv, rv[tid * 16 + c]);
            g_bestval[n0 + tid] = bv;
        }
    }
}

// ---------------------------------------------------------------------------
// Exact fp32 rescoring of candidates; warp per candidate.
// ---------------------------------------------------------------------------
__global__ void exact_kernel(const float* __restrict__ latent,
                             const float* __restrict__ coords) {
    int gw   = (blockIdx.x * blockDim.x + threadIdx.x) >> 5;
    int lane = threadIdx.x & 31;
    int nw   = (gridDim.x * blockDim.x) >> 5;
    int cnt  = g_cnt[0];
    if (cnt > CAP) cnt = CAP;

    for (int i = gw; i < cnt; i += nw) {
        uint32_t pk = g_list[i];
        int n = pk >> 12, k = pk & 4095;
        float4 x = ((const float4*)(latent + (size_t)n * DIM))[lane];
        float4 c = ((const float4*)(coords + (size_t)k * DIM))[lane];
        float d = fmaf(x.x, c.x, fmaf(x.y, c.y, fmaf(x.z, c.z, x.w * c.w)));
        #pragma unroll
        for (int o = 16; o; o >>= 1) d += __shfl_xor_sync(~0u, d, o);
        if (lane == 0) {
            float s = fmaf(-2.0f, d, g_c2[k]);
            unsigned long long key =
                ((unsigned long long)fkey(s) << 32) | (unsigned int)k;
            atomicMin(&g_best[n], key);
        }
    }
}

// ---------------------------------------------------------------------------
extern "C" void kernel_launch(void* const* d_in, const int* in_sizes, int n_in,
                              void* d_out, int out_size) {
    const float* latent;
    const float* coords;
    if (in_sizes[0] == NPTS * DIM) {
        latent = (const float*)d_in[0];
        coords = (const float*)d_in[1];
    } else {
        latent = (const float*)d_in[1];
        coords = (const float*)d_in[0];
    }
    float* out = (float*)d_out;

    const int smem_bytes = 131072 + 16384;   // A 64K + B 2x32K + c2 16K
    cudaFuncSetAttribute(phase_kernel<1>,
                         cudaFuncAttributeMaxDynamicSharedMemorySize, smem_bytes);
    cudaFuncSetAttribute(phase_kernel<2>,
                         cudaFuncAttributeMaxDynamicSharedMemorySize, smem_bytes);

    init_best_kernel<<<NPTS / 256, 256>>>();
    prep_a<<<NPTS / 8, 256>>>(latent);
    prep_b<<<KC / 8, 256>>>(coords);
    reduce_kernel<<<1, 512>>>();
    phase_kernel<1><<<NPTS / BN, 512, smem_bytes>>>();
    phase_kernel<2><<<NPTS / BN, 512, smem_bytes>>>();
    exact_kernel<<<1024, 256>>>(latent, coords);
    final_kernel<<<NPTS / 256, 256>>>(out);
}

// round 16
// speedup vs baseline: 1.1914x; 1.1914x over previous
#include <cuda_runtime.h>
#include <cuda_bf16.h>
#include <cstdint>

#define NPTS 65536
#define KC   4096
#define DIM  128
#define BN   256          // rows per CTA
#define BK   128
#define NT   (KC / BK)    // 32 tiles
#define CAP  (1 << 24)

// Device scratch (allocation-free rule)
__device__ __nv_bfloat16 g_a0[NPTS * DIM];
__device__ __nv_bfloat16 g_b0[KC * DIM];
__device__ __align__(16) float2 g_an[NPTS];  // {2||a1||, 2||a0||}
__device__ __align__(16) float2 g_bn[KC];    // {||b||, ||b1||}
__device__ __align__(16) float  g_c2[KC];    // exact ||b||^2
__device__ float g_bmax[2];
__device__ unsigned long long g_best[NPTS];
__device__ int g_cnt[1];
__device__ uint32_t g_list[CAP];             // (n<<12)|k

// ---------------------------------------------------------------------------
__device__ __forceinline__ uint32_t smem_u32(const void* p) {
    uint32_t a;
    asm("{ .reg .u64 t; cvta.to.shared.u64 t, %1; cvt.u32.u64 %0, t; }"
        : "=r"(a) : "l"(p));
    return a;
}
__device__ __forceinline__ uint32_t fkey(float f) {      // order-preserving
    uint32_t u = __float_as_uint(f);
    return (u & 0x80000000u) ? ~u : (u | 0x80000000u);
}
__device__ __forceinline__ float fkey_inv(uint32_t e) {
    return (e & 0x80000000u) ? __uint_as_float(e & 0x7FFFFFFFu)
                             : __uint_as_float(~e);
}
#define LDSM_X4(r0, r1, r2, r3, addr) \
    asm volatile("ldmatrix.sync.aligned.m8n8.x4.shared.b16 {%0,%1,%2,%3}, [%4];" \
                 : "=r"(r0), "=r"(r1), "=r"(r2), "=r"(r3) : "r"(addr))
#define MMA_BF16(c, a, b0v, b1v) \
    asm volatile("mma.sync.aligned.m16n8k16.row.col.f32.bf16.bf16.f32 " \
                 "{%0,%1,%2,%3}, {%4,%5,%6,%7}, {%8,%9}, {%0,%1,%2,%3};" \
                 : "+f"((c)[0]), "+f"((c)[1]), "+f"((c)[2]), "+f"((c)[3]) \
                 : "r"((a)[0]), "r"((a)[1]), "r"((a)[2]), "r"((a)[3]), \
                   "r"(b0v), "r"(b1v))
__device__ __forceinline__ void cp16(uint32_t dst, const void* src) {
    asm volatile("cp.async.cg.shared.global [%0], [%1], 16;"
                 :: "r"(dst), "l"(src));
}
#define CP_COMMIT() asm volatile("cp.async.commit_group;" ::: "memory")
#define CP_WAIT0()  asm volatile("cp.async.wait_group 0;" ::: "memory")

// ---------------------------------------------------------------------------
// Prologues (identical to R12/R13 — validated rel_err 0.0)
// ---------------------------------------------------------------------------
__global__ void prep_a(const float* __restrict__ in) {
    int row  = blockIdx.x * 8 + (threadIdx.x >> 5);
    int lane = threadIdx.x & 31;
    float4 v = ((const float4*)(in + (size_t)row * DIM))[lane];
    float va[4] = {v.x, v.y, v.z, v.w};
    __nv_bfloat16 h[4];
    float n0 = 0.f, n1 = 0.f;
    #pragma unroll
    for (int j = 0; j < 4; ++j) {
        h[j] = __float2bfloat16(va[j]);
        float a0 = __bfloat162float(h[j]);
        float r  = va[j] - a0;
        n0 = fmaf(a0, a0, n0);
        n1 = fmaf(r, r, n1);
    }
    *(uint2*)(g_a0 + (size_t)row * DIM + lane * 4) = *(const uint2*)h;
    #pragma unroll
    for (int o = 16; o; o >>= 1) {
        n0 += __shfl_xor_sync(~0u, n0, o);
        n1 += __shfl_xor_sync(~0u, n1, o);
    }
    if (lane == 0) g_an[row] = make_float2(2.f * sqrtf(n1), 2.f * sqrtf(n0));
}
__global__ void prep_b(const float* __restrict__ in) {
    int row  = blockIdx.x * 8 + (threadIdx.x >> 5);
    int lane = threadIdx.x & 31;
    float4 v = ((const float4*)(in + (size_t)row * DIM))[lane];
    float va[4] = {v.x, v.y, v.z, v.w};
    __nv_bfloat16 h[4];
    float nb = 0.f, n1 = 0.f;
    #pragma unroll
    for (int j = 0; j < 4; ++j) {
        h[j] = __float2bfloat16(va[j]);
        float b0 = __bfloat162float(h[j]);
        float r  = va[j] - b0;
        nb = fmaf(va[j], va[j], nb);
        n1 = fmaf(r, r, n1);
    }
    *(uint2*)(g_b0 + (size_t)row * DIM + lane * 4) = *(const uint2*)h;
    #pragma unroll
    for (int o = 16; o; o >>= 1) {
        nb += __shfl_xor_sync(~0u, nb, o);
        n1 += __shfl_xor_sync(~0u, n1, o);
    }
    if (lane == 0) {
        g_c2[row] = nb;
        g_bn[row] = make_float2(sqrtf(nb), sqrtf(n1));
    }
}
__global__ void reduce_kernel() {
    __shared__ float s0[512], s1[512];
    int t = threadIdx.x;
    float m0 = 0.f, m1 = 0.f;
    for (int k = t; k < KC; k += 512) {
        float2 b = g_bn[k];
        m0 = fmaxf(m0, b.x);
        m1 = fmaxf(m1, b.y);
    }
    s0[t] = m0; s1[t] = m1;
    __syncthreads();
    for (int o = 256; o; o >>= 1) {
        if (t < o) {
            s0[t] = fmaxf(s0[t], s0[t + o]);
            s1[t] = fmaxf(s1[t], s1[t + o]);
        }
        __syncthreads();
    }
    if (t == 0) { g_bmax[0] = s0[0]; g_bmax[1] = s1[0]; g_cnt[0] = 0; }
}
__global__ void init_best_kernel() {
    int i = blockIdx.x * blockDim.x + threadIdx.x;
    if (i < NPTS) g_best[i] = 0xFFFFFFFFFFFFFFFFull;
}
__global__ void final_kernel(float* __restrict__ out) {
    int i = blockIdx.x * blockDim.x + threadIdx.x;
    if (i < NPTS) out[i] = (float)(uint32_t)(g_best[i] & 0xFFFFFFFFull);
}

// ---------------------------------------------------------------------------
// FUSED single-pass: 1-pass a0*b0 HMMA (R13-validated GEMM path) + CTA-shared
// prefix-min + certified candidate push, all in one sweep over K.
// 512 threads = 16 warps, 4(M) x 4(N); warp tile 64(M) x 32(N), BN=256.
// smem: A @0 (64K), B double @64K/96K, c2 @128K (16K), rowminU @144K (1K).
// ---------------------------------------------------------------------------
__global__ __launch_bounds__(512) void fused_kernel() {
    extern __shared__ char smem[];
    const uint32_t sbase = smem_u32(smem);
    const float* c2s = (const float*)(smem + 131072);
    unsigned int* rowminU = (unsigned int*)(smem + 147456);

    const int tid = threadIdx.x;
    const int L   = tid & 31;
    const int wid = tid >> 5;
    const int wm  = wid & 3;
    const int wn  = wid >> 2;
    const int n0  = blockIdx.x * BN;

    // stage A once: 256 rows x 256B, swizzled (plain stores — validated)
    #pragma unroll
    for (int it = 0; it < 8; ++it) {
        int Gi = tid + it * 512;
        int row = Gi >> 4, g = Gi & 15;
        uint4 v = *((const uint4*)(g_a0 + (size_t)(n0 + row) * DIM) + g);
        *(uint4*)(smem + row * 256 + ((g ^ (row & 7)) << 4)) = v;
    }
    // stage full-K c2 once (16 KB)
    #pragma unroll
    for (int it = 0; it < 2; ++it) {
        int Gi = tid + it * 512;
        cp16(sbase + 131072 + Gi * 16, g_c2 + Gi * 4);
    }
    // init prefix-min
    if (tid < BN) rowminU[tid] = 0xFFFFFFFFu;

    auto stage_b = [&](int st, int k0) {
        #pragma unroll
        for (int it = 0; it < 4; ++it) {
            int Gi = tid + it * 512;
            int row = Gi >> 4, g = Gi & 15;
            uint32_t dst = sbase + 65536 + st * 32768 +
                           row * 256 + ((g ^ (row & 7)) << 4);
            cp16(dst, g_b0 + (size_t)(k0 + row) * DIM + g * 8);
        }
    };
    stage_b(0, 0);
    CP_COMMIT();

    // ldmatrix lane constants (validated R7-R13)
    const int aRow = ((L >> 3) & 1) * 8 + (L & 7);
    const int aG   = L >> 4;
    const int sxa  = (L & 7);
    const int bRow = (L >> 4) * 8 + (L & 7);
    const int bG   = (L >> 3) & 1;
    const int sxb  = (L & 7);
    uint32_t aAddrB[4];
    #pragma unroll
    for (int bi = 0; bi < 4; ++bi)
        aAddrB[bi] = sbase + (64 * wm + 16 * bi + aRow) * 256;
    const uint32_t bOff = (32 * wn + bRow) * 256;

    // per-slot constants: margins (validated R12/R13 math)
    const float bm0 = g_bmax[0], bm1 = g_bmax[1];
    float anx[4][2], any[4][2], Cn[4][2];
    int rowS[4][2];
    #pragma unroll
    for (int bi = 0; bi < 4; ++bi)
        #pragma unroll
        for (int h = 0; h < 2; ++h) {
            int rs = 64 * wm + 16 * bi + 8 * h + (L >> 2);
            rowS[bi][h] = rs;
            float2 an = g_an[n0 + rs];
            anx[bi][h] = an.x; any[bi][h] = an.y;
            Cn[bi][h]  = an.x * bm0 + an.y * bm1 + 0.02f;
        }

    for (int kt = 0; kt < NT; ++kt) {
        const int st = kt & 1;
        const int k0 = kt * BK;

        CP_WAIT0();
        __syncthreads();
        if (kt + 1 < NT) { stage_b(st ^ 1, k0 + BK); CP_COMMIT(); }

        const uint32_t bAddr = sbase + 65536 + st * 32768 + bOff;

        float acc[4][4][4];
        #pragma unroll
        for (int bi = 0; bi < 4; ++bi)
            #pragma unroll
            for (int nb = 0; nb < 4; ++nb)
                #pragma unroll
                for (int c = 0; c < 4; ++c) acc[bi][nb][c] = 0.0f;

        #pragma unroll
        for (int kk = 0; kk < 8; ++kk) {
            uint32_t a[4][4];
            #pragma unroll
            for (int bi = 0; bi < 4; ++bi) {
                uint32_t ad = aAddrB[bi] + (((2 * kk + aG) ^ sxa) << 4);
                LDSM_X4(a[bi][0], a[bi][1], a[bi][2], a[bi][3], ad);
            }
            uint32_t b[2][4];
            #pragma unroll
            for (int i2 = 0; i2 < 2; ++i2) {
                uint32_t bd = bAddr + i2 * 4096 + (((2 * kk + bG) ^ sxb) << 4);
                LDSM_X4(b[i2][0], b[i2][1], b[i2][2], b[i2][3], bd);
            }
            #pragma unroll
            for (int bi = 0; bi < 4; ++bi)
                #pragma unroll
                for (int nb = 0; nb < 4; ++nb) {
                    const uint32_t* q = b[nb >> 1];
                    if (nb & 1) MMA_BF16(acc[bi][nb], a[bi], q[2], q[3]);
                    else        MMA_BF16(acc[bi][nb], a[bi], q[0], q[1]);
                }
        }

        // ---- pass 1: update CTA prefix-min (per-slot local min -> shfl
        //      across the 4 lanes sharing the row -> one smem atomicMin) ----
        float lmin[4][2];
        #pragma unroll
        for (int bi = 0; bi < 4; ++bi)
            #pragma unroll
            for (int h = 0; h < 2; ++h) lmin[bi][h] = 3.0e38f;
        #pragma unroll
        for (int nb = 0; nb < 4; ++nb) {
            int kc = k0 + 32 * wn + 8 * nb + 2 * (L & 3);
            float c2a = c2s[kc], c2b = c2s[kc + 1];
            #pragma unroll
            for (int bi = 0; bi < 4; ++bi)
                #pragma unroll
                for (int h = 0; h < 2; ++h) {
                    float s0 = fmaf(-2.0f, acc[bi][nb][h * 2 + 0], c2a);
                    float s1 = fmaf(-2.0f, acc[bi][nb][h * 2 + 1], c2b);
                    lmin[bi][h] = fminf(lmin[bi][h], fminf(s0, s1));
                }
        }
        #pragma unroll
        for (int bi = 0; bi < 4; ++bi)
            #pragma unroll
            for (int h = 0; h < 2; ++h) {
                float m = lmin[bi][h];
                m = fminf(m, __shfl_xor_sync(~0u, m, 1));
                m = fminf(m, __shfl_xor_sync(~0u, m, 2));
                if ((L & 3) == 0)
                    atomicMin(&rowminU[rowS[bi][h]], fkey(m));
            }
        __syncthreads();

        // ---- pass 2: certified test against prefix-min threshold ----
        float thr[4][2];
        #pragma unroll
        for (int bi = 0; bi < 4; ++bi)
            #pragma unroll
            for (int h = 0; h < 2; ++h)
                thr[bi][h] = fkey_inv(rowminU[rowS[bi][h]]) + Cn[bi][h];
        #pragma unroll
        for (int nb = 0; nb < 4; ++nb) {
            int kc = k0 + 32 * wn + 8 * nb + 2 * (L & 3);
            float c2a = c2s[kc], c2b = c2s[kc + 1];
            float4 bn4 = __ldg((const float4*)(g_bn + kc));
            #pragma unroll
            for (int bi = 0; bi < 4; ++bi)
                #pragma unroll
                for (int h = 0; h < 2; ++h) {
                    float s0 = fmaf(-2.0f, acc[bi][nb][h * 2 + 0], c2a);
                    float s1 = fmaf(-2.0f, acc[bi][nb][h * 2 + 1], c2b);
                    int nr = n0 + rowS[bi][h];
                    if (s0 <= fmaf(anx[bi][h], bn4.x,
                                   fmaf(any[bi][h], bn4.y, thr[bi][h]))) {
                        int p = atomicAdd(g_cnt, 1);
                        if (p < CAP)
                            g_list[p] = ((uint32_t)nr << 12) | (uint32_t)kc;
                    }
                    if (s1 <= fmaf(anx[bi][h], bn4.z,
                                   fmaf(any[bi][h], bn4.w, thr[bi][h]))) {
                        int p = atomicAdd(g_cnt, 1);
                        if (p < CAP)
                            g_list[p] = ((uint32_t)nr << 12) | (uint32_t)(kc + 1);
                    }
                }
        }
    }
}

// ---------------------------------------------------------------------------
// Exact fp32 rescoring of candidates; warp per candidate.
// ---------------------------------------------------------------------------
__global__ void exact_kernel(const float* __restrict__ latent,
                             const float* __restrict__ coords) {
    int gw   = (blockIdx.x * blockDim.x + threadIdx.x) >> 5;
    int lane = threadIdx.x & 31;
    int nw   = (gridDim.x * blockDim.x) >> 5;
    int cnt  = g_cnt[0];
    if (cnt > CAP) cnt = CAP;

    for (int i = gw; i < cnt; i += nw) {
        uint32_t pk = g_list[i];
        int n = pk >> 12, k = pk & 4095;
        float4 x = ((const float4*)(latent + (size_t)n * DIM))[lane];
        float4 c = ((const float4*)(coords + (size_t)k * DIM))[lane];
        float d = fmaf(x.x, c.x, fmaf(x.y, c.y, fmaf(x.z, c.z, x.w * c.w)));
        #pragma unroll
        for (int o = 16; o; o >>= 1) d += __shfl_xor_sync(~0u, d, o);
        if (lane == 0) {
            float s = fmaf(-2.0f, d, g_c2[k]);
            unsigned long long key =
                ((unsigned long long)fkey(s) << 32) | (unsigned int)k;
            atomicMin(&g_best[n], key);
        }
    }
}

// ---------------------------------------------------------------------------
extern "C" void kernel_launch(void* const* d_in, const int* in_sizes, int n_in,
                              void* d_out, int out_size) {
    const float* latent;
    const float* coords;
    if (in_sizes[0] == NPTS * DIM) {
        latent = (const float*)d_in[0];
        coords = (const float*)d_in[1];
    } else {
        latent = (const float*)d_in[1];
        coords = (const float*)d_in[0];
    }
    float* out = (float*)d_out;

    const int smem_bytes = 147456 + 1024;  // A 64K + B 2x32K + c2 16K + rowmin 1K
    cudaFuncSetAttribute(fused_kernel,
                         cudaFuncAttributeMaxDynamicSharedMemorySize, smem_bytes);

    init_best_kernel<<<NPTS / 256, 256>>>();
    prep_a<<<NPTS / 8, 256>>>(latent);
    prep_b<<<KC / 8, 256>>>(coords);
    reduce_kernel<<<1, 512>>>();
    fused_kernel<<<NPTS / BN, 512, smem_bytes>>>();
    exact_kernel<<<1024, 256>>>(latent, coords);
    final_kernel<<<NPTS / 256, 256>>>(out);
}

// round 17
// speedup vs baseline: 1.2258x; 1.0289x over previous
#include <cuda_runtime.h>
#include <cuda_bf16.h>
#include <cstdint>

#define NPTS 65536
#define KC   4096
#define DIM  128
#define BN   256          // rows per CTA
#define BK   128
#define NT   (KC / BK)    // 32 tiles
#define CAP  (1 << 24)

// Device scratch (allocation-free rule)
__device__ __nv_bfloat16 g_a0[NPTS * DIM];
__device__ __nv_bfloat16 g_b0[KC * DIM];
__device__ __align__(16) float2 g_an[NPTS];  // {2||a1||, 2||a0||}
__device__ __align__(16) float2 g_bn[KC];    // {||b||, ||b1||}
__device__ __align__(16) float  g_c2[KC];    // exact ||b||^2
__device__ float g_bmax[2];
__device__ unsigned long long g_best[NPTS];
__device__ int g_cnt[1];
__device__ uint32_t g_list[CAP];             // (n<<12)|k

// smem layout (bytes)
#define SM_A    0
#define SM_B    65536
#define SM_C2   131072
#define SM_BN   147456
#define SM_RMIN 180224
#define SM_TOT  181248

// ---------------------------------------------------------------------------
__device__ __forceinline__ uint32_t smem_u32(const void* p) {
    uint32_t a;
    asm("{ .reg .u64 t; cvta.to.shared.u64 t, %1; cvt.u32.u64 %0, t; }"
        : "=r"(a) : "l"(p));
    return a;
}
__device__ __forceinline__ uint32_t fkey(float f) {      // order-preserving
    uint32_t u = __float_as_uint(f);
    return (u & 0x80000000u) ? ~u : (u | 0x80000000u);
}
__device__ __forceinline__ float fkey_inv(uint32_t e) {
    return (e & 0x80000000u) ? __uint_as_float(e & 0x7FFFFFFFu)
                             : __uint_as_float(~e);
}
#define LDSM_X4(r0, r1, r2, r3, addr) \
    asm volatile("ldmatrix.sync.aligned.m8n8.x4.shared.b16 {%0,%1,%2,%3}, [%4];" \
                 : "=r"(r0), "=r"(r1), "=r"(r2), "=r"(r3) : "r"(addr))
#define MMA_BF16(c, a, b0v, b1v) \
    asm volatile("mma.sync.aligned.m16n8k16.row.col.f32.bf16.bf16.f32 " \
                 "{%0,%1,%2,%3}, {%4,%5,%6,%7}, {%8,%9}, {%0,%1,%2,%3};" \
                 : "+f"((c)[0]), "+f"((c)[1]), "+f"((c)[2]), "+f"((c)[3]) \
                 : "r"((a)[0]), "r"((a)[1]), "r"((a)[2]), "r"((a)[3]), \
                   "r"(b0v), "r"(b1v))
__device__ __forceinline__ void cp16(uint32_t dst, const void* src) {
    asm volatile("cp.async.cg.shared.global [%0], [%1], 16;"
                 :: "r"(dst), "l"(src));
}
#define CP_COMMIT() asm volatile("cp.async.commit_group;" ::: "memory")
#define CP_WAIT0()  asm volatile("cp.async.wait_group 0;" ::: "memory")

// ---------------------------------------------------------------------------
// Prologues (identical to R12/R13/R16 — validated rel_err 0.0)
// ---------------------------------------------------------------------------
__global__ void prep_a(const float* __restrict__ in) {
    int row  = blockIdx.x * 8 + (threadIdx.x >> 5);
    int lane = threadIdx.x & 31;
    float4 v = ((const float4*)(in + (size_t)row * DIM))[lane];
    float va[4] = {v.x, v.y, v.z, v.w};
    __nv_bfloat16 h[4];
    float n0 = 0.f, n1 = 0.f;
    #pragma unroll
    for (int j = 0; j < 4; ++j) {
        h[j] = __float2bfloat16(va[j]);
        float a0 = __bfloat162float(h[j]);
        float r  = va[j] - a0;
        n0 = fmaf(a0, a0, n0);
        n1 = fmaf(r, r, n1);
    }
    *(uint2*)(g_a0 + (size_t)row * DIM + lane * 4) = *(const uint2*)h;
    #pragma unroll
    for (int o = 16; o; o >>= 1) {
        n0 += __shfl_xor_sync(~0u, n0, o);
        n1 += __shfl_xor_sync(~0u, n1, o);
    }
    if (lane == 0) g_an[row] = make_float2(2.f * sqrtf(n1), 2.f * sqrtf(n0));
}
__global__ void prep_b(const float* __restrict__ in) {
    int row  = blockIdx.x * 8 + (threadIdx.x >> 5);
    int lane = threadIdx.x & 31;
    float4 v = ((const float4*)(in + (size_t)row * DIM))[lane];
    float va[4] = {v.x, v.y, v.z, v.w};
    __nv_bfloat16 h[4];
    float nb = 0.f, n1 = 0.f;
    #pragma unroll
    for (int j = 0; j < 4; ++j) {
        h[j] = __float2bfloat16(va[j]);
        float b0 = __bfloat162float(h[j]);
        float r  = va[j] - b0;
        nb = fmaf(va[j], va[j], nb);
        n1 = fmaf(r, r, n1);
    }
    *(uint2*)(g_b0 + (size_t)row * DIM + lane * 4) = *(const uint2*)h;
    #pragma unroll
    for (int o = 16; o; o >>= 1) {
        nb += __shfl_xor_sync(~0u, nb, o);
        n1 += __shfl_xor_sync(~0u, n1, o);
    }
    if (lane == 0) {
        g_c2[row] = nb;
        g_bn[row] = make_float2(sqrtf(nb), sqrtf(n1));
    }
}
__global__ void reduce_kernel() {
    __shared__ float s0[512], s1[512];
    int t = threadIdx.x;
    float m0 = 0.f, m1 = 0.f;
    for (int k = t; k < KC; k += 512) {
        float2 b = g_bn[k];
        m0 = fmaxf(m0, b.x);
        m1 = fmaxf(m1, b.y);
    }
    s0[t] = m0; s1[t] = m1;
    __syncthreads();
    for (int o = 256; o; o >>= 1) {
        if (t < o) {
            s0[t] = fmaxf(s0[t], s0[t + o]);
            s1[t] = fmaxf(s1[t], s1[t + o]);
        }
        __syncthreads();
    }
    if (t == 0) { g_bmax[0] = s0[0]; g_bmax[1] = s1[0]; g_cnt[0] = 0; }
}
__global__ void init_best_kernel() {
    int i = blockIdx.x * blockDim.x + threadIdx.x;
    if (i < NPTS) g_best[i] = 0xFFFFFFFFFFFFFFFFull;
}
__global__ void final_kernel(float* __restrict__ out) {
    int i = blockIdx.x * blockDim.x + threadIdx.x;
    if (i < NPTS) out[i] = (float)(uint32_t)(g_best[i] & 0xFFFFFFFFull);
}

// ---------------------------------------------------------------------------
// FUSED single-pass (R16 logic, leaks plugged): a0*b0 HMMA + CTA prefix-min +
// certified push. bn cached in SMEM; scores computed once (in-place in acc).
// 512 threads = 16 warps, 4(M) x 4(N); warp tile 64(M) x 32(N), BN=256.
// ---------------------------------------------------------------------------
__global__ __launch_bounds__(512) void fused_kernel() {
    extern __shared__ char smem[];
    const uint32_t sbase = smem_u32(smem);
    const float*  c2s = (const float*)(smem + SM_C2);
    const float2* bns = (const float2*)(smem + SM_BN);
    unsigned int* rowminU = (unsigned int*)(smem + SM_RMIN);

    const int tid = threadIdx.x;
    const int L   = tid & 31;
    const int wid = tid >> 5;
    const int wm  = wid & 3;
    const int wn  = wid >> 2;
    const int n0  = blockIdx.x * BN;

    // stage A once: 256 rows x 256B, swizzled (plain stores — validated)
    #pragma unroll
    for (int it = 0; it < 8; ++it) {
        int Gi = tid + it * 512;
        int row = Gi >> 4, g = Gi & 15;
        uint4 v = *((const uint4*)(g_a0 + (size_t)(n0 + row) * DIM) + g);
        *(uint4*)(smem + row * 256 + ((g ^ (row & 7)) << 4)) = v;
    }
    // stage c2 (16 KB) + bn (32 KB) once
    #pragma unroll
    for (int it = 0; it < 2; ++it) {
        int Gi = tid + it * 512;
        cp16(sbase + SM_C2 + Gi * 16, g_c2 + Gi * 4);
    }
    #pragma unroll
    for (int it = 0; it < 4; ++it) {
        int Gi = tid + it * 512;
        cp16(sbase + SM_BN + Gi * 16, (const char*)g_bn + Gi * 16);
    }
    if (tid < BN) rowminU[tid] = 0xFFFFFFFFu;

    auto stage_b = [&](int st, int k0) {
        #pragma unroll
        for (int it = 0; it < 4; ++it) {
            int Gi = tid + it * 512;
            int row = Gi >> 4, g = Gi & 15;
            uint32_t dst = sbase + SM_B + st * 32768 +
                           row * 256 + ((g ^ (row & 7)) << 4);
            cp16(dst, g_b0 + (size_t)(k0 + row) * DIM + g * 8);
        }
    };
    stage_b(0, 0);
    CP_COMMIT();

    // ldmatrix lane constants (validated R7-R16)
    const int aRow = ((L >> 3) & 1) * 8 + (L & 7);
    const int aG   = L >> 4;
    const int sxa  = (L & 7);
    const int bRow = (L >> 4) * 8 + (L & 7);
    const int bG   = (L >> 3) & 1;
    const int sxb  = (L & 7);
    uint32_t aAddrB[4];
    #pragma unroll
    for (int bi = 0; bi < 4; ++bi)
        aAddrB[bi] = sbase + (64 * wm + 16 * bi + aRow) * 256;
    const uint32_t bOff = (32 * wn + bRow) * 256;

    // per-slot constants: margins (validated R12/R13/R16 math)
    const float bm0 = g_bmax[0], bm1 = g_bmax[1];
    float anx[4][2], any[4][2], Cn[4][2];
    int rowS[4][2];
    #pragma unroll
    for (int bi = 0; bi < 4; ++bi)
        #pragma unroll
        for (int h = 0; h < 2; ++h) {
            int rs = 64 * wm + 16 * bi + 8 * h + (L >> 2);
            rowS[bi][h] = rs;
            float2 an = g_an[n0 + rs];
            anx[bi][h] = an.x; any[bi][h] = an.y;
            Cn[bi][h]  = an.x * bm0 + an.y * bm1 + 0.02f;
        }

    for (int kt = 0; kt < NT; ++kt) {
        const int st = kt & 1;
        const int k0 = kt * BK;

        CP_WAIT0();
        __syncthreads();
        if (kt + 1 < NT) { stage_b(st ^ 1, k0 + BK); CP_COMMIT(); }

        const uint32_t bAddr = sbase + SM_B + st * 32768 + bOff;

        float acc[4][4][4];
        #pragma unroll
        for (int bi = 0; bi < 4; ++bi)
            #pragma unroll
            for (int nb = 0; nb < 4; ++nb)
                #pragma unroll
                for (int c = 0; c < 4; ++c) acc[bi][nb][c] = 0.0f;

        #pragma unroll
        for (int kk = 0; kk < 8; ++kk) {
            uint32_t a[4][4];
            #pragma unroll
            for (int bi = 0; bi < 4; ++bi) {
                uint32_t ad = aAddrB[bi] + (((2 * kk + aG) ^ sxa) << 4);
                LDSM_X4(a[bi][0], a[bi][1], a[bi][2], a[bi][3], ad);
            }
            uint32_t b[2][4];
            #pragma unroll
            for (int i2 = 0; i2 < 2; ++i2) {
                uint32_t bd = bAddr + i2 * 4096 + (((2 * kk + bG) ^ sxb) << 4);
                LDSM_X4(b[i2][0], b[i2][1], b[i2][2], b[i2][3], bd);
            }
            #pragma unroll
            for (int bi = 0; bi < 4; ++bi)
                #pragma unroll
                for (int nb = 0; nb < 4; ++nb) {
                    const uint32_t* q = b[nb >> 1];
                    if (nb & 1) MMA_BF16(acc[bi][nb], a[bi], q[2], q[3]);
                    else        MMA_BF16(acc[bi][nb], a[bi], q[0], q[1]);
                }
        }

        // ---- pass 1: scores IN PLACE + CTA prefix-min update ----
        float lmin[4][2];
        #pragma unroll
        for (int bi = 0; bi < 4; ++bi)
            #pragma unroll
            for (int h = 0; h < 2; ++h) lmin[bi][h] = 3.0e38f;
        #pragma unroll
        for (int nb = 0; nb < 4; ++nb) {
            int kc = k0 + 32 * wn + 8 * nb + 2 * (L & 3);
            float c2a = c2s[kc], c2b = c2s[kc + 1];
            #pragma unroll
            for (int bi = 0; bi < 4; ++bi)
                #pragma unroll
                for (int h = 0; h < 2; ++h) {
                    float s0 = fmaf(-2.0f, acc[bi][nb][h * 2 + 0], c2a);
                    float s1 = fmaf(-2.0f, acc[bi][nb][h * 2 + 1], c2b);
                    acc[bi][nb][h * 2 + 0] = s0;   // overwrite: scores
                    acc[bi][nb][h * 2 + 1] = s1;
                    lmin[bi][h] = fminf(lmin[bi][h], fminf(s0, s1));
                }
        }
        #pragma unroll
        for (int bi = 0; bi < 4; ++bi)
            #pragma unroll
            for (int h = 0; h < 2; ++h) {
                float m = lmin[bi][h];
                m = fminf(m, __shfl_xor_sync(~0u, m, 1));
                m = fminf(m, __shfl_xor_sync(~0u, m, 2));
                if ((L & 3) == 0)
                    atomicMin(&rowminU[rowS[bi][h]], fkey(m));
            }
        __syncthreads();

        // ---- pass 2: certified test against prefix-min threshold ----
        float thr[4][2];
        #pragma unroll
        for (int bi = 0; bi < 4; ++bi)
            #pragma unroll
            for (int h = 0; h < 2; ++h)
                thr[bi][h] = fkey_inv(rowminU[rowS[bi][h]]) + Cn[bi][h];
        #pragma unroll
        for (int nb = 0; nb < 4; ++nb) {
            int kc = k0 + 32 * wn + 8 * nb + 2 * (L & 3);
            float4 bn4 = *(const float4*)(bns + kc);   // SMEM, no L2
            #pragma unroll
            for (int bi = 0; bi < 4; ++bi)
                #pragma unroll
                for (int h = 0; h < 2; ++h) {
                    float s0 = acc[bi][nb][h * 2 + 0];
                    float s1 = acc[bi][nb][h * 2 + 1];
                    int nr = n0 + rowS[bi][h];
                    if (s0 <= fmaf(anx[bi][h], bn4.x,
                                   fmaf(any[bi][h], bn4.y, thr[bi][h]))) {
                        int p = atomicAdd(g_cnt, 1);
                        if (p < CAP)
                            g_list[p] = ((uint32_t)nr << 12) | (uint32_t)kc;
                    }
                    if (s1 <= fmaf(anx[bi][h], bn4.z,
                                   fmaf(any[bi][h], bn4.w, thr[bi][h]))) {
                        int p = atomicAdd(g_cnt, 1);
                        if (p < CAP)
                            g_list[p] = ((uint32_t)nr << 12) | (uint32_t)(kc + 1);
                    }
                }
        }
    }
}

// ---------------------------------------------------------------------------
// Exact fp32 rescoring of candidates; warp per candidate.
// ---------------------------------------------------------------------------
__global__ void exact_kernel(const float* __restrict__ latent,
                             const float* __restrict__ coords) {
    int gw   = (blockIdx.x * blockDim.x + threadIdx.x) >> 5;
    int lane = threadIdx.x & 31;
    int nw   = (gridDim.x * blockDim.x) >> 5;
    int cnt  = g_cnt[0];
    if (cnt > CAP) cnt = CAP;

    for (int i = gw; i < cnt; i += nw) {
        uint32_t pk = g_list[i];
        int n = pk >> 12, k = pk & 4095;
        float4 x = ((const float4*)(latent + (size_t)n * DIM))[lane];
        float4 c = ((const float4*)(coords + (size_t)k * DIM))[lane];
        float d = fmaf(x.x, c.x, fmaf(x.y, c.y, fmaf(x.z, c.z, x.w * c.w)));
        #pragma unroll
        for (int o = 16; o; o >>= 1) d += __shfl_xor_sync(~0u, d, o);
        if (lane == 0) {
            float s = fmaf(-2.0f, d, g_c2[k]);
            unsigned long long key =
                ((unsigned long long)fkey(s) << 32) | (unsigned int)k;
            atomicMin(&g_best[n], key);
        }
    }
}

// ---------------------------------------------------------------------------
extern "C" void kernel_launch(void* const* d_in, const int* in_sizes, int n_in,
                              void* d_out, int out_size) {
    const float* latent;
    const float* coords;
    if (in_sizes[0] == NPTS * DIM) {
        latent = (const float*)d_in[0];
        coords = (const float*)d_in[1];
    } else {
        latent = (const float*)d_in[1];
        coords = (const float*)d_in[0];
    }
    float* out = (float*)d_out;

    cudaFuncSetAttribute(fused_kernel,
                         cudaFuncAttributeMaxDynamicSharedMemorySize, SM_TOT);

    init_best_kernel<<<NPTS / 256, 256>>>();
    prep_a<<<NPTS / 8, 256>>>(latent);
    prep_b<<<KC / 8, 256>>>(coords);
    reduce_kernel<<<1, 512>>>();
    fused_kernel<<<NPTS / BN, 512, SM_TOT>>>();
    exact_kernel<<<1024, 256>>>(latent, coords);
    final_kernel<<<NPTS / 256, 256>>>(out);
}